// round 13
// baseline (speedup 1.0000x reference)
#include <cuda_runtime.h>
#include <cstdint>

#define BB       4
#define NPTS     4096
#define TPB      512
#define NWARP    (TPB / 32)               // 16
#define QPT      4                        // register queries per thread
#define QPB      (TPB * QPT)              // 2048 queries per block
#define QSPLIT   2                        // query tiles per batch
#define NSLICE   32                       // target slices per batch
#define TSL      (NPTS / NSLICE)          // 128 targets per slice
#define TPR      (TSL / 2)                // 64 target pairs in smem
#define NBLK1    (BB * QSPLIT * NSLICE)   // 256 blocks, 2/SM resident
#define NQ_TOTAL (2 * BB * NPTS)          // 32768 min slots (16384 src + 16384 tgt)

// Running mins as float BIT PATTERNS (distances >= 0 -> uint order == float
// order). Both halves combined via REDG.MIN (exact & idempotent -> bit-
// deterministic). memset to 0x7F7F7F7F (3.39e38) each launch.
__device__ unsigned g_minq[NQ_TOTAL];     // 128 KB
__device__ int      g_ticket;             // zero-init; last block resets it

__device__ __forceinline__ uint64_t pk2(float lo, float hi) {
    uint64_t r;
    asm("mov.b64 %0, {%1, %2};" : "=l"(r) : "f"(lo), "f"(hi));
    return r;
}
__device__ __forceinline__ uint64_t fma2(uint64_t a, uint64_t b, uint64_t c) {
    uint64_t d;
    asm("fma.rn.f32x2 %0, %1, %2, %3;" : "=l"(d) : "l"(a), "l"(b), "l"(c));
    return d;
}
__device__ __forceinline__ uint64_t add2(uint64_t a, uint64_t b) {
    uint64_t d;
    asm("add.rn.f32x2 %0, %1, %2;" : "=l"(d) : "l"(a), "l"(b));
    return d;
}
__device__ __forceinline__ void unpk(uint64_t v, float& lo, float& hi) {
    asm("mov.b64 {%0, %1}, %2;" : "=f"(lo), "=f"(hi) : "l"(v));
}
// Butterfly fold step: lane keeps (sel ? odd : even), gives the other away;
// the xor-delta partner does the mirror image.
__device__ __forceinline__ float bfold(float even, float odd, int sel, int delta) {
    float give = sel ? even : odd;
    float recv = __shfl_xor_sync(0xFFFFFFFFu, give, delta);
    float keep = sel ? odd : even;
    return fminf(keep, recv);
}

// SYMMETRIC kernel: each distance computed ONCE, feeds BOTH direction mins.
// 2 BLOCKS PER SM (launch_bounds(512,2)): one block's mainloop warps cover the
// other's butterfly/atomic/barrier stalls. Block = (2048-query tile) x
// (128-target slice). Targets PAIR-PACKED in smem: sP={x0,x1,y0,y1},
// sQ={z0,z1,w0,w1} (w=|t|^2). Per target-pair step per thread:
//   2 LDS.128 + 4 x [1 ADD2 + 3 FFMA2] -> 8 full distances
//   + 8 FMNMX q-side + 4-deep t-side chains; 9-shfl butterfly per 8 targets.
__global__ void __launch_bounds__(TPB, 2)
chamfer_sym(const float* __restrict__ src, const float* __restrict__ tgt,
            float* __restrict__ out)
{
    __shared__ float4 sP[TPR];            // {x0,x1,y0,y1}
    __shared__ float4 sQ[TPR];            // {z0,z1,w0,w1}
    __shared__ float  sWT[NWARP][TSL];    // per-warp t-side partial mins (8 KB)

    int b    = blockIdx.x >> 6;           // batch
    int rest = blockIdx.x & 63;
    int qsub = rest >> 5;                 // query half
    int tc   = rest & 31;                 // target slice
    int wid  = threadIdx.x >> 5, lid = threadIdx.x & 31;

    const float* qb = src + ((size_t)b * NPTS + qsub * QPB) * 3;
    const float* db = tgt + ((size_t)b * NPTS + tc * TSL) * 3;

    if (threadIdx.x < TPR) {
        int p = threadIdx.x;
        const float* t = db + 6 * p;
        float x0 = t[0], y0 = t[1], z0 = t[2];
        float x1 = t[3], y1 = t[4], z1 = t[5];
        sP[p] = make_float4(x0, x1, y0, y1);
        sQ[p] = make_float4(z0, z1,
                            fmaf(x0, x0, fmaf(y0, y0, z0 * z0)),
                            fmaf(x1, x1, fmaf(y1, y1, z1 * z1)));
    }

    // 4 register queries, duplicated packs (32 regs).
    uint64_t QXd[QPT], QYd[QPT], QZd[QPT], X2d[QPT];
    float qmin[QPT];
    #pragma unroll
    for (int q = 0; q < QPT; q++) {
        int qa = threadIdx.x + q * TPB;
        float ax = qb[3 * qa], ay = qb[3 * qa + 1], az = qb[3 * qa + 2];
        float x2 = fmaf(ax, ax, fmaf(ay, ay, az * az));
        QXd[q] = pk2(-2.f * ax, -2.f * ax);
        QYd[q] = pk2(-2.f * ay, -2.f * ay);
        QZd[q] = pk2(-2.f * az, -2.f * az);
        X2d[q] = pk2(x2, x2);
        qmin[q] = 3.4e38f;
    }
    __syncthreads();

    const ulonglong2* P1 = (const ulonglong2*)sP;  // .x={x0,x1} .y={y0,y1}
    const ulonglong2* P2 = (const ulonglong2*)sQ;  // .x={z0,z1} .y={w0,w1}

    int b0 = lid & 1, b1 = (lid >> 1) & 1, b2 = (lid >> 2) & 1;

    #pragma unroll 2
    for (int po = 0; po < TPR / 4; po++) {        // 16 windows
        float W[8];
        #pragma unroll
        for (int pi = 0; pi < 4; pi++) {          // 4 target pairs = 8 targets
            int p = po * 4 + pi;
            ulonglong2 t1 = P1[p];
            ulonglong2 t2 = P2[p];
            float T0, T1;
            #pragma unroll
            for (int q = 0; q < QPT; q++) {
                uint64_t acc = add2(t2.y, X2d[q]);        // {w0+x2, w1+x2}
                acc = fma2(QZd[q], t2.x, acc);
                acc = fma2(QYd[q], t1.y, acc);
                acc = fma2(QXd[q], t1.x, acc);            // full distances
                float d0, d1;
                unpk(acc, d0, d1);
                qmin[q] = fminf(qmin[q], fminf(d0, d1));  // short carried chain
                T0 = (q == 0) ? d0 : fminf(T0, d0);       // t-side chains
                T1 = (q == 0) ? d1 : fminf(T1, d1);
            }
            W[2 * pi]     = T0;                           // target po*8 + 2pi
            W[2 * pi + 1] = T1;                           // target po*8 + 2pi+1
        }
        // 9-shfl butterfly: after xor 1/2/4, lane holds target (lane&7).
        float R0 = bfold(W[0], W[1], b0, 1);
        float R1 = bfold(W[2], W[3], b0, 1);
        float R2 = bfold(W[4], W[5], b0, 1);
        float R3 = bfold(W[6], W[7], b0, 1);
        float S0 = bfold(R0, R1, b1, 2);
        float S1 = bfold(R2, R3, b1, 2);
        float U  = bfold(S0, S1, b2, 4);
        U = fminf(U, __shfl_xor_sync(0xFFFFFFFFu, U, 8));
        U = fminf(U, __shfl_xor_sync(0xFFFFFFFFu, U, 16));
        if (lid < 8) sWT[wid][po * 8 + lid] = U;
    }

    // q-side: REDG.MIN on bit patterns (exact & idempotent -> deterministic).
    int qg = b * NPTS + qsub * QPB + threadIdx.x;
    #pragma unroll
    for (int q = 0; q < QPT; q++)
        atomicMin(&g_minq[qg + q * TPB], __float_as_uint(qmin[q]));

    // t-side: fold the 16 warp rows; 2 query-tile blocks share each target
    // slot -> REDG.MIN combine.
    __syncthreads();
    if (threadIdx.x < TSL) {
        int p = threadIdx.x;
        float v = sWT[0][p];
        #pragma unroll
        for (int w = 1; w < NWARP; w++) v = fminf(v, sWT[w][p]);
        atomicMin(&g_minq[NPTS * BB + b * NPTS + tc * TSL + p],
                  __float_as_uint(v));
    }

    // Ticket: last block sums everything.
    __threadfence();
    __syncthreads();
    __shared__ int amLast;
    if (threadIdx.x == 0) {
        int prev = atomicAdd(&g_ticket, 1);
        amLast = (prev == NBLK1 - 1);
    }
    __syncthreads();
    if (!amLast) return;

    __threadfence();   // acquire: all blocks' writes visible
    float sum = 0.f;
    const uint4* G = (const uint4*)g_minq;            // 8192 uint4
    #pragma unroll
    for (int jj = 0; jj < NQ_TOTAL / 4 / TPB; jj++) { // 16 iters
        uint4 u = __ldcg(&G[threadIdx.x + jj * TPB]);
        sum += (__uint_as_float(u.x) + __uint_as_float(u.y))
             + (__uint_as_float(u.z) + __uint_as_float(u.w));
    }
    #pragma unroll
    for (int off = 16; off > 0; off >>= 1)
        sum += __shfl_down_sync(0xFFFFFFFFu, sum, off);

    __shared__ float ws[NWARP];
    if ((threadIdx.x & 31) == 0) ws[threadIdx.x >> 5] = sum;
    __syncthreads();
    if (threadIdx.x == 0) {
        float tot = 0.f;
        #pragma unroll
        for (int i = 0; i < NWARP; i++) tot += ws[i];      // fixed order
        out[0] = tot * (1.0f / (float)(BB * NPTS));
        g_ticket = 0;                                      // reset for replay
    }
}

extern "C" void kernel_launch(void* const* d_in, const int* in_sizes, int n_in,
                              void* d_out, int out_size)
{
    const float* src = (const float*)d_in[0];
    const float* tgt = (const float*)d_in[1];
    float* out = (float*)d_out;

    void* minq_addr = nullptr;
    cudaGetSymbolAddress(&minq_addr, g_minq);
    // 0x7F7F7F7F = 3.39e38f sentinel, far above any real squared distance.
    cudaMemsetAsync(minq_addr, 0x7F, NQ_TOTAL * sizeof(unsigned));

    chamfer_sym<<<NBLK1, TPB>>>(src, tgt, out);
}

// round 16
// speedup vs baseline: 1.0402x; 1.0402x over previous
#include <cuda_runtime.h>
#include <cstdint>

#define BB       4
#define NPTS     4096
#define TPB      1024
#define NWARP    (TPB / 32)               // 32
#define QPT      4                        // register queries per thread
#define NSLICE   32                       // target slices per batch
#define TSL      (NPTS / NSLICE)          // 128 targets per slice
#define TPR      (TSL / 2)                // 64 target pairs in smem
#define NBLK1    (BB * NSLICE)            // 128 blocks, 1/SM, 8 warps/SMSP
#define NQS      (BB * NPTS)              // 16384 source-side slots
#define NQ_TOTAL (2 * BB * NPTS)          // + 16384 target-side slots

// Running mins stored as COMPLEMENTED float bit patterns: for dist >= 0,
// smaller float -> smaller bits -> LARGER ~bits, so min(dist) == max(~bits)
// and ZERO-INIT is the natural identity for atomicMax -> no memset node.
// The ticket block re-zeroes the atomic half after summing each replay.
// [0,16384): source side (atomicMax, 32 writer blocks).
// [16384,32768): target side (plain STG, unique owner block per slot).
__device__ unsigned g_minq[NQ_TOTAL];     // 128 KB, zero-init at load
__device__ int      g_ticket;             // zero-init; ticket block resets it

__device__ __forceinline__ uint64_t pk2(float lo, float hi) {
    uint64_t r;
    asm("mov.b64 %0, {%1, %2};" : "=l"(r) : "f"(lo), "f"(hi));
    return r;
}
__device__ __forceinline__ uint64_t fma2(uint64_t a, uint64_t b, uint64_t c) {
    uint64_t d;
    asm("fma.rn.f32x2 %0, %1, %2, %3;" : "=l"(d) : "l"(a), "l"(b), "l"(c));
    return d;
}
__device__ __forceinline__ uint64_t add2(uint64_t a, uint64_t b) {
    uint64_t d;
    asm("add.rn.f32x2 %0, %1, %2;" : "=l"(d) : "l"(a), "l"(b));
    return d;
}
__device__ __forceinline__ void unpk(uint64_t v, float& lo, float& hi) {
    asm("mov.b64 {%0, %1}, %2;" : "=f"(lo), "=f"(hi) : "l"(v));
}
// Butterfly fold step: lane keeps (sel ? odd : even), gives the other away;
// the xor-delta partner does the mirror image.
__device__ __forceinline__ float bfold(float even, float odd, int sel, int delta) {
    float give = sel ? even : odd;
    float recv = __shfl_xor_sync(0xFFFFFFFFu, give, delta);
    float keep = sel ? odd : even;
    return fminf(keep, recv);
}

// SYMMETRIC kernel: each distance computed ONCE, feeds BOTH direction mins.
// Block = batch b x 128-target slice, 1024 threads, 4 register queries each
// (<=64 regs -> 8 warps/SMSP). Targets PAIR-PACKED in smem:
// sP[p]={x0,x1,y0,y1}, sQ[p]={z0,z1,w0,w1} (w=|t|^2). Per target-pair step:
//   2 LDS.128 + 4 x [1 ADD2 + 3 FFMA2] -> 8 full distances
//   + 8 FMNMX q-side mins + 6 FMNMX t-side chains (alu pipe, parallel).
// t-side flush per 8-target window: 9-shfl butterfly -> lane&7 holds the
// warp-min -> sWT -> cross-warp fold. Min is exact => order-independent.
__global__ void __launch_bounds__(TPB, 1)
chamfer_sym(const float* __restrict__ src, const float* __restrict__ tgt,
            float* __restrict__ out)
{
    __shared__ float4 sP[TPR];            // {x0,x1,y0,y1}
    __shared__ float4 sQ[TPR];            // {z0,z1,w0,w1}
    __shared__ float  sWT[NWARP][TSL];    // per-warp t-side partial mins (16 KB)

    int b   = blockIdx.x >> 5;
    int tc  = blockIdx.x & 31;
    int wid = threadIdx.x >> 5, lid = threadIdx.x & 31;

    const float* qb = src + (size_t)b * NPTS * 3;
    const float* db = tgt + ((size_t)b * NPTS + tc * TSL) * 3;

    if (threadIdx.x < TPR) {
        int p = threadIdx.x;
        const float* t = db + 6 * p;
        float x0 = t[0], y0 = t[1], z0 = t[2];
        float x1 = t[3], y1 = t[4], z1 = t[5];
        sP[p] = make_float4(x0, x1, y0, y1);
        sQ[p] = make_float4(z0, z1,
                            fmaf(x0, x0, fmaf(y0, y0, z0 * z0)),
                            fmaf(x1, x1, fmaf(y1, y1, z1 * z1)));
    }

    // 4 register queries, duplicated packs (32 regs).
    uint64_t QXd[QPT], QYd[QPT], QZd[QPT], X2d[QPT];
    float qmin[QPT];
    #pragma unroll
    for (int q = 0; q < QPT; q++) {
        int qa = threadIdx.x + q * TPB;
        float ax = qb[3 * qa], ay = qb[3 * qa + 1], az = qb[3 * qa + 2];
        float x2 = fmaf(ax, ax, fmaf(ay, ay, az * az));
        QXd[q] = pk2(-2.f * ax, -2.f * ax);
        QYd[q] = pk2(-2.f * ay, -2.f * ay);
        QZd[q] = pk2(-2.f * az, -2.f * az);
        X2d[q] = pk2(x2, x2);
        qmin[q] = 3.4e38f;
    }
    __syncthreads();

    const ulonglong2* P1 = (const ulonglong2*)sP;  // .x={x0,x1} .y={y0,y1}
    const ulonglong2* P2 = (const ulonglong2*)sQ;  // .x={z0,z1} .y={w0,w1}

    int b0 = lid & 1, b1 = (lid >> 1) & 1, b2 = (lid >> 2) & 1;

    #pragma unroll 2
    for (int po = 0; po < TPR / 4; po++) {        // 16 windows
        float W[8];
        #pragma unroll
        for (int pi = 0; pi < 4; pi++) {          // 4 target pairs = 8 targets
            int p = po * 4 + pi;
            ulonglong2 t1 = P1[p];
            ulonglong2 t2 = P2[p];
            float T0, T1;
            #pragma unroll
            for (int q = 0; q < QPT; q++) {
                uint64_t acc = add2(t2.y, X2d[q]);        // {w0+x2, w1+x2}
                acc = fma2(QZd[q], t2.x, acc);
                acc = fma2(QYd[q], t1.y, acc);
                acc = fma2(QXd[q], t1.x, acc);            // full distances
                float d0, d1;
                unpk(acc, d0, d1);
                qmin[q] = fminf(qmin[q], fminf(d0, d1));  // q-side running min
                T0 = (q == 0) ? d0 : fminf(T0, d0);       // t-side chains
                T1 = (q == 0) ? d1 : fminf(T1, d1);
            }
            W[2 * pi]     = T0;                           // target po*8 + 2pi
            W[2 * pi + 1] = T1;                           // target po*8 + 2pi+1
        }
        // 9-shfl butterfly: after xor 1/2/4, lane holds target (lane&7).
        float R0 = bfold(W[0], W[1], b0, 1);
        float R1 = bfold(W[2], W[3], b0, 1);
        float R2 = bfold(W[4], W[5], b0, 1);
        float R3 = bfold(W[6], W[7], b0, 1);
        float S0 = bfold(R0, R1, b1, 2);
        float S1 = bfold(R2, R3, b1, 2);
        float U  = bfold(S0, S1, b2, 4);
        U = fminf(U, __shfl_xor_sync(0xFFFFFFFFu, U, 8));
        U = fminf(U, __shfl_xor_sync(0xFFFFFFFFu, U, 16));
        if (lid < 8) sWT[wid][po * 8 + lid] = U;
    }

    // q-side: atomicMax on COMPLEMENTED bits (exact & idempotent ->
    // bit-deterministic; zero-init is the identity -> no memset node).
    int qg = b * NPTS + threadIdx.x;
    #pragma unroll
    for (int q = 0; q < QPT; q++)
        atomicMax(&g_minq[qg + q * TPB], ~__float_as_uint(qmin[q]));

    // t-side: fold the 32 warp rows; unique owner -> plain complemented STG.
    __syncthreads();
    if (threadIdx.x < TSL) {
        int p = threadIdx.x;
        float v = sWT[0][p];
        #pragma unroll
        for (int w = 1; w < NWARP; w++) v = fminf(v, sWT[w][p]);
        g_minq[NQS + b * NPTS + tc * TSL + p] = ~__float_as_uint(v);
    }

    // Ticket: last block sums everything, then re-zeroes the atomic half.
    __threadfence();
    __syncthreads();
    __shared__ int amLast;
    if (threadIdx.x == 0) {
        int prev = atomicAdd(&g_ticket, 1);
        amLast = (prev == NBLK1 - 1);
    }
    __syncthreads();
    if (!amLast) return;

    __threadfence();   // acquire: all blocks' writes visible
    float sum = 0.f;
    const uint4* G = (const uint4*)g_minq;            // 8192 uint4
    #pragma unroll
    for (int jj = 0; jj < NQ_TOTAL / 4 / TPB; jj++) { // 8 iters
        uint4 u = __ldcg(&G[threadIdx.x + jj * TPB]);
        sum += (__uint_as_float(~u.x) + __uint_as_float(~u.y))
             + (__uint_as_float(~u.z) + __uint_as_float(~u.w));
    }
    // reset the atomicMax half to its zero identity for the next replay
    // (same addresses this thread just read -> program order is enough)
    uint4* Gw = (uint4*)g_minq;
    #pragma unroll
    for (int jj = 0; jj < NQS / 4 / TPB; jj++)        // 4 iters
        Gw[threadIdx.x + jj * TPB] = make_uint4(0u, 0u, 0u, 0u);

    #pragma unroll
    for (int off = 16; off > 0; off >>= 1)
        sum += __shfl_down_sync(0xFFFFFFFFu, sum, off);

    __shared__ float ws[NWARP];
    if ((threadIdx.x & 31) == 0) ws[threadIdx.x >> 5] = sum;
    __syncthreads();
    if (threadIdx.x == 0) {
        float tot = 0.f;
        #pragma unroll
        for (int i = 0; i < NWARP; i++) tot += ws[i];      // fixed order
        out[0] = tot * (1.0f / (float)(BB * NPTS));
        g_ticket = 0;                                      // reset for replay
    }
}

extern "C" void kernel_launch(void* const* d_in, const int* in_sizes, int n_in,
                              void* d_out, int out_size)
{
    const float* src = (const float*)d_in[0];
    const float* tgt = (const float*)d_in[1];
    float* out = (float*)d_out;

    chamfer_sym<<<NBLK1, TPB>>>(src, tgt, out);   // single graph node
}